// round 13
// baseline (speedup 1.0000x reference)
#include <cuda_runtime.h>
#include <cuda_bf16.h>
#include <math_constants.h>
#include <cstdint>

// Shapes: latents [16,2048,512] -> [32768,512], embedding [8192,512]
constexpr int DDIM  = 512;
constexpr int KCODE = 8192;
constexpr int NROWS = 16 * 2048;

constexpr int TM = 128;
constexpr int TN = 128;
constexpr int KB = 64;           // bf16 elems per stage row = 128B
constexpr int NSTAGE = 3;
constexpr int NKS = DDIM / KB;   // 8
constexpr int NRT = NROWS / TM;  // 256
constexpr int NCT = KCODE / TN;  // 64
constexpr int NTILE = NRT * NCT; // 16384
constexpr int GRID  = 296;       // 148 SMs x 2 CTAs (persistent)

constexpr int   NCAND  = 128;
constexpr float MARGIN = 1e-3f;  // >= 2*bf16 screen err (5.4e-4) + tie win (1.9e-4)

constexpr uint32_t STAGE_BYTES = TM * KB * 2;               // 16384
constexpr uint32_t B_OFF       = NSTAGE * STAGE_BYTES;      // 49152
constexpr uint32_t SMEM_BYTES  = 2 * NSTAGE * STAGE_BYTES;  // 98304

// ---------------- scratch ----------------
__device__ __nv_bfloat16 g_Xb[NROWS * DDIM];
__device__ __nv_bfloat16 g_Eb[KCODE * DDIM];
__device__ float    g_e2[KCODE];
__device__ float    g_x2[NROWS];
__device__ unsigned g_rowmin[NROWS];            // float-ordered keys
__device__ int      g_cnt[NROWS];
__device__ int      g_cand[NROWS * NCAND];

// ---------------- helpers ----------------
__device__ __forceinline__ uint32_t smem_u32(const void* p) {
    uint32_t a;
    asm("{ .reg .u64 t; cvta.to.shared.u64 t, %1; cvt.u32.u64 %0, t; }" : "=r"(a) : "l"(p));
    return a;
}
__device__ __forceinline__ unsigned fkey(float f) {          // order-preserving
    unsigned b = __float_as_uint(f);
    return b ^ (unsigned)(((int)b >> 31) | 0x80000000);
}
__device__ __forceinline__ float funkey(unsigned k) {
    unsigned b = k ^ (unsigned)((~(int)k >> 31) | 0x80000000);
    return __uint_as_float(b);
}
__device__ __forceinline__ void mma16(float* d, const uint32_t* a, const uint32_t* b) {
    asm volatile(
        "mma.sync.aligned.m16n8k16.row.col.f32.bf16.bf16.f32 "
        "{%0,%1,%2,%3}, {%4,%5,%6,%7}, {%8,%9}, {%0,%1,%2,%3};"
        : "+f"(d[0]), "+f"(d[1]), "+f"(d[2]), "+f"(d[3])
        : "r"(a[0]), "r"(a[1]), "r"(a[2]), "r"(a[3]), "r"(b[0]), "r"(b[1]));
}
#define LDSM_X4(r0, r1, r2, r3, addr)                                            \
    asm volatile("ldmatrix.sync.aligned.m8n8.x4.shared.b16 {%0,%1,%2,%3}, [%4];" \
        : "=r"(r0), "=r"(r1), "=r"(r2), "=r"(r3) : "r"(addr))
#define CP_ASYNC16(dst, src) \
    asm volatile("cp.async.cg.shared.global [%0], [%1], 16;" :: "r"(dst), "l"(src) : "memory")
#define CP_COMMIT()  asm volatile("cp.async.commit_group;" ::: "memory")
#define CP_WAIT1()   asm volatile("cp.async.wait_group 1;" ::: "memory")

// ---------------------------------------------------------------------------
// Kernel 1: norms (R1-proven structure) + bf16 convert + rowmin/cnt init
// ---------------------------------------------------------------------------
__global__ void prep_kernel(const float* __restrict__ X, const float* __restrict__ E) {
    int w    = (blockIdx.x * blockDim.x + threadIdx.x) >> 5;
    int lane = threadIdx.x & 31;
    if (w >= KCODE + NROWS) return;
    bool isE = (w < KCODE);
    int  r   = isE ? w : (w - KCODE);
    const float4* p = (const float4*)(isE ? (E + (size_t)r * DDIM) : (X + (size_t)r * DDIM));

    float s = 0.f;
#pragma unroll
    for (int i = 0; i < 4; i++) {
        float4 v = p[lane + 32 * i];
        s += v.x * v.x + v.y * v.y + v.z * v.z + v.w * v.w;
    }
#pragma unroll
    for (int o = 16; o > 0; o >>= 1) s += __shfl_xor_sync(0xffffffffu, s, o);
    if (lane == 0) {
        if (isE) g_e2[r] = s;
        else { g_x2[r] = s; g_rowmin[r] = 0xFFFFFFFFu; g_cnt[r] = 0; }
    }

    __nv_bfloat162* dst = (__nv_bfloat162*)((isE ? g_Eb : g_Xb) + (size_t)r * DDIM);
#pragma unroll
    for (int i = 0; i < 4; i++) {
        float4 v = p[lane + 32 * i];
        dst[(lane + 32 * i) * 2 + 0] = __floats2bfloat162_rn(v.x, v.y);
        dst[(lane + 32 * i) * 2 + 1] = __floats2bfloat162_rn(v.z, v.w);
    }
}

// ---------------------------------------------------------------------------
// Kernel 2: persistent bf16 GEMM. Each CTA loops tiles (bid, bid+296, ...).
// Continuous chunk counter c (8 per tile), buf = c%3; prefetching chunk c+2
// naturally overlaps the next tile's first stages with this tile's epilogue.
// Epilogue: rmin -> atomicMin; candidate append GATED on rmin<=Tf.
// ---------------------------------------------------------------------------
__global__ __launch_bounds__(256, 2) void vq_mma_kernel() {
    extern __shared__ char smem[];
    const uint32_t sb = smem_u32(smem);
    const int tid = threadIdx.x;
    const int wid = tid >> 5, lane = tid & 31;
    const int g = lane >> 2, tig = lane & 3;
    const int wm = wid & 3, wn = wid >> 2;          // warp grid 4 x 2
    const int bid = blockIdx.x;
    const int nt  = (NTILE - bid + GRID - 1) / GRID;   // tiles for this CTA

    // prefetch chunk c (tile w=c/8 of this CTA, K-offset (c&7)*KB, buf c%3)
    auto prefetch = [&](int c) {
        if (c >= nt * 8) return;
        const int idx  = bid + (c >> 3) * GRID;
        const int ks   = (c & 7) * KB;
        const int prow = (idx >> 6) * TM;              // col-tile fastest
        const int pcol = (idx & 63) * TN;
        const uint32_t sbase = sb + (uint32_t)(c % 3) * STAGE_BYTES;
#pragma unroll
        for (int i = 0; i < 4; i++) {                  // A: 1024 16B chunks
            int u = tid + 256 * i, row = u >> 3, ch = u & 7;
            const void* src = g_Xb + (size_t)(prow + row) * DDIM + ks + ch * 8;
            CP_ASYNC16(sbase + (uint32_t)(row * 128 + (ch ^ (row & 7)) * 16), src);
        }
#pragma unroll
        for (int i = 0; i < 4; i++) {                  // B: 1024 16B chunks
            int u = tid + 256 * i, row = u >> 3, ch = u & 7;
            const void* src = g_Eb + (size_t)(pcol + row) * DDIM + ks + ch * 8;
            CP_ASYNC16(B_OFF + sbase + (uint32_t)(row * 128 + (ch ^ (row & 7)) * 16), src);
        }
    };

    const int lrow = lane & 7, sel = lane >> 3;
    int arow[2]; const int acb = sel >> 1;
#pragma unroll
    for (int mt = 0; mt < 2; mt++) arow[mt] = wm * 32 + mt * 16 + lrow + (sel & 1) * 8;
    int brow[4]; const int bcb = sel & 1;
#pragma unroll
    for (int ntp = 0; ntp < 4; ntp++) brow[ntp] = wn * 64 + ntp * 16 + (sel >> 1) * 8 + lrow;

    prefetch(0); CP_COMMIT();
    prefetch(1); CP_COMMIT();

    for (int w = 0; w < nt; w++) {
        const int idx  = bid + w * GRID;
        const int row0 = (idx >> 6) * TM;
        const int col0 = (idx & 63) * TN;

        float acc[2][8][4];
#pragma unroll
        for (int mt = 0; mt < 2; mt++)
#pragma unroll
            for (int nt2 = 0; nt2 < 8; nt2++)
#pragma unroll
                for (int q = 0; q < 4; q++) acc[mt][nt2][q] = 0.f;

#pragma unroll 1
        for (int ks = 0; ks < NKS; ks++) {
            const int c = w * 8 + ks;
            CP_WAIT1();
            __syncthreads();
            prefetch(c + 2);                           // next-tile overlap at ks>=6
            CP_COMMIT();

            const uint32_t As = sb + (uint32_t)(c % 3) * STAGE_BYTES;
            const uint32_t Bs = As + B_OFF;
#pragma unroll
            for (int s16 = 0; s16 < 4; s16++) {
                uint32_t a[2][4];
#pragma unroll
                for (int mt = 0; mt < 2; mt++) {
                    int cc = 2 * s16 + acb;
                    uint32_t ad = As + arow[mt] * 128 + ((cc ^ (arow[mt] & 7)) * 16);
                    LDSM_X4(a[mt][0], a[mt][1], a[mt][2], a[mt][3], ad);
                }
                uint32_t b[8][2];
#pragma unroll
                for (int ntp = 0; ntp < 4; ntp++) {
                    int cc = 2 * s16 + bcb;
                    uint32_t bd = Bs + brow[ntp] * 128 + ((cc ^ (brow[ntp] & 7)) * 16);
                    LDSM_X4(b[2 * ntp][0], b[2 * ntp][1], b[2 * ntp + 1][0], b[2 * ntp + 1][1], bd);
                }
#pragma unroll
                for (int nt2 = 0; nt2 < 8; nt2++) {
                    mma16(acc[0][nt2], a[0], b[nt2]);
                    mma16(acc[1][nt2], a[1], b[nt2]);
                }
            }
        }

        // ---- epilogue (registers + atomics only; smem untouched) ----
#pragma unroll
        for (int mt = 0; mt < 2; mt++) {
#pragma unroll
            for (int rr = 0; rr < 2; rr++) {
                const int row = row0 + wm * 32 + mt * 16 + g + rr * 8;
                float s0[8], s1[8];
                float rmin = CUDART_INF_F;
#pragma unroll
                for (int nt2 = 0; nt2 < 8; nt2++) {
                    int col = col0 + wn * 64 + nt2 * 8 + 2 * tig;
                    s0[nt2] = __ldg(&g_e2[col])     - 2.0f * acc[mt][nt2][rr * 2];
                    s1[nt2] = __ldg(&g_e2[col + 1]) - 2.0f * acc[mt][nt2][rr * 2 + 1];
                    rmin = fminf(rmin, fminf(s0[nt2], s1[nt2]));
                }
                rmin = fminf(rmin, __shfl_xor_sync(0xffffffffu, rmin, 1));
                rmin = fminf(rmin, __shfl_xor_sync(0xffffffffu, rmin, 2));
                unsigned mykey = fkey(rmin);
                unsigned oldkey = 0xFFFFFFFFu;
                if (tig == 0) oldkey = atomicMin(&g_rowmin[row], mykey);
                oldkey = __shfl_sync(0xffffffffu, oldkey, lane & ~3);
                const float Tf = funkey(min(oldkey, mykey)) + MARGIN;
                if (rmin <= Tf) {                      // gate: ~5% of (row,strip)
#pragma unroll
                    for (int nt2 = 0; nt2 < 8; nt2++) {
                        int col = col0 + wn * 64 + nt2 * 8 + 2 * tig;
                        if (s0[nt2] <= Tf) {
                            int i2 = atomicAdd(&g_cnt[row], 1);
                            if (i2 < NCAND) g_cand[row * NCAND + i2] = col;
                        }
                        if (s1[nt2] <= Tf) {
                            int i2 = atomicAdd(&g_cnt[row], 1);
                            if (i2 < NCAND) g_cand[row * NCAND + i2] = col + 1;
                        }
                    }
                }
            }
        }
    }
}

// ---------------------------------------------------------------------------
// Kernel 3: candidate rescue + fused gather/STE. One warp per row.
// Exact dist form byte-identical to the rel_err==0.0-proven path.
// ---------------------------------------------------------------------------
__global__ __launch_bounds__(256) void rescue_gather_kernel(
    const float* __restrict__ X, const float* __restrict__ E,
    float* __restrict__ out) {
    int w    = (blockIdx.x * blockDim.x + threadIdx.x) >> 5;
    int lane = threadIdx.x & 31;
    if (w >= NROWS) return;
    const int row = w;
    const int cnt = g_cnt[row];
    const float x2v = g_x2[row];
    const float* xr = X + (size_t)row * DDIM;
    unsigned long long best = ~0ull;

    if (cnt > NCAND) {
        for (int k = lane; k < KCODE; k += 32) {      // overflow fallback
            const float* er = E + (size_t)k * DDIM;
            float acc = 0.f;
            for (int d = 0; d < DDIM; d++) acc += xr[d] * er[d];
            float t    = x2v + g_e2[k];
            float dist = t - 2.0f * acc;
            unsigned long long p =
                ((unsigned long long)__float_as_uint(dist) << 32) | (unsigned)k;
            best = (p < best) ? p : best;
        }
    } else {
        for (int i = lane; i < cnt; i += 32) {
            int k = g_cand[row * NCAND + i];
            const float* er = E + (size_t)k * DDIM;
            float acc = 0.f;
            for (int d = 0; d < DDIM; d++) acc += xr[d] * er[d];
            float t    = x2v + g_e2[k];
            float dist = t - 2.0f * acc;              // exact R1-form dist
            unsigned long long p =
                ((unsigned long long)__float_as_uint(dist) << 32) | (unsigned)k;
            best = (p < best) ? p : best;
        }
    }
#pragma unroll
    for (int o = 16; o > 0; o >>= 1) {
        unsigned long long q = __shfl_xor_sync(0xffffffffu, best, o);
        best = (q < best) ? q : best;
    }
    const int c = (int)(unsigned)(best & 0xffffffffull);

    // fused gather + STE rounding: out = x + (e - x)
    const float4* ep = (const float4*)(E + (size_t)c * DDIM);
    const float4* xp = (const float4*)xr;
    float4* op = (float4*)(out + (size_t)row * DDIM);
#pragma unroll
    for (int i = 0; i < 4; i++) {
        float4 e = ep[lane + 32 * i];
        float4 x = xp[lane + 32 * i];
        float4 o;
        o.x = __fadd_rn(x.x, __fsub_rn(e.x, x.x));
        o.y = __fadd_rn(x.y, __fsub_rn(e.y, x.y));
        o.z = __fadd_rn(x.z, __fsub_rn(e.z, x.z));
        o.w = __fadd_rn(x.w, __fsub_rn(e.w, x.w));
        op[lane + 32 * i] = o;
    }
}

// ---------------------------------------------------------------------------
extern "C" void kernel_launch(void* const* d_in, const int* in_sizes, int n_in,
                              void* d_out, int out_size) {
    const float* X = (const float*)d_in[0];
    const float* E = (const float*)d_in[1];
    float* out = (float*)d_out;

    cudaFuncSetAttribute(vq_mma_kernel, cudaFuncAttributeMaxDynamicSharedMemorySize,
                         SMEM_BYTES);

    int warps = KCODE + NROWS;
    prep_kernel<<<(warps * 32 + 255) / 256, 256>>>(X, E);
    vq_mma_kernel<<<GRID, 256, SMEM_BYTES>>>();
    rescue_gather_kernel<<<NROWS / 8, 256>>>(X, E, out);
}

// round 14
// speedup vs baseline: 1.0538x; 1.0538x over previous
#include <cuda_runtime.h>
#include <cuda_bf16.h>
#include <math_constants.h>
#include <cstdint>

// Shapes: latents [16,2048,512] -> [32768,512], embedding [8192,512]
constexpr int DDIM  = 512;
constexpr int KCODE = 8192;
constexpr int NROWS = 16 * 2048;

constexpr int TM = 128;
constexpr int TN = 128;
constexpr int KB = 64;           // bf16 elems per stage row = 128B
constexpr int NSTAGE = 3;
constexpr int NKS = DDIM / KB;   // 8
constexpr int NRT = NROWS / TM;  // 256
constexpr int NCT = KCODE / TN;  // 64

constexpr float MARGIN = 1e-3f;  // 2*bf16 err (5.4e-4) + tie win (1.9e-4) + quant (1.25e-4)
constexpr float Q_OFF  = -0.03f;     // u8 score quantization
constexpr float Q_STEP = 2.5e-4f;
constexpr float Q_INV  = 1.0f / Q_STEP;

constexpr uint32_t STAGE_BYTES = TM * KB * 2;               // 16384
constexpr uint32_t B_OFF       = NSTAGE * STAGE_BYTES;      // 49152
constexpr uint32_t SMEM_BYTES  = 2 * NSTAGE * STAGE_BYTES;  // 98304

// ---------------- scratch ----------------
__device__ __nv_bfloat16 g_Xb[NROWS * DDIM];
__device__ __nv_bfloat16 g_Eb[KCODE * DDIM];
__device__ float    g_e2[KCODE];
__device__ float    g_x2[NROWS];
__device__ uint8_t  g_score8[(size_t)NROWS * KCODE];  // 256 MB quantized scores
__device__ unsigned g_rowmin[NROWS];                  // float-ordered keys (exact fp32)

// ---------------- helpers ----------------
__device__ __forceinline__ uint32_t smem_u32(const void* p) {
    uint32_t a;
    asm("{ .reg .u64 t; cvta.to.shared.u64 t, %1; cvt.u32.u64 %0, t; }" : "=r"(a) : "l"(p));
    return a;
}
__device__ __forceinline__ unsigned fkey(float f) {          // order-preserving
    unsigned b = __float_as_uint(f);
    return b ^ (unsigned)(((int)b >> 31) | 0x80000000);
}
__device__ __forceinline__ float funkey(unsigned k) {
    unsigned b = k ^ (unsigned)((~(int)k >> 31) | 0x80000000);
    return __uint_as_float(b);
}
__device__ __forceinline__ void mma16(float* d, const uint32_t* a, const uint32_t* b) {
    asm volatile(
        "mma.sync.aligned.m16n8k16.row.col.f32.bf16.bf16.f32 "
        "{%0,%1,%2,%3}, {%4,%5,%6,%7}, {%8,%9}, {%0,%1,%2,%3};"
        : "+f"(d[0]), "+f"(d[1]), "+f"(d[2]), "+f"(d[3])
        : "r"(a[0]), "r"(a[1]), "r"(a[2]), "r"(a[3]), "r"(b[0]), "r"(b[1]));
}
#define LDSM_X4(r0, r1, r2, r3, addr)                                            \
    asm volatile("ldmatrix.sync.aligned.m8n8.x4.shared.b16 {%0,%1,%2,%3}, [%4];" \
        : "=r"(r0), "=r"(r1), "=r"(r2), "=r"(r3) : "r"(addr))
#define CP_ASYNC16(dst, src) \
    asm volatile("cp.async.cg.shared.global [%0], [%1], 16;" :: "r"(dst), "l"(src) : "memory")
#define CP_COMMIT()  asm volatile("cp.async.commit_group;" ::: "memory")
#define CP_WAIT1()   asm volatile("cp.async.wait_group 1;" ::: "memory")

// ---------------------------------------------------------------------------
// Kernel 1: norms (R1-proven structure) + bf16 convert + rowmin init
// ---------------------------------------------------------------------------
__global__ void prep_kernel(const float* __restrict__ X, const float* __restrict__ E) {
    int w    = (blockIdx.x * blockDim.x + threadIdx.x) >> 5;
    int lane = threadIdx.x & 31;
    if (w >= KCODE + NROWS) return;
    bool isE = (w < KCODE);
    int  r   = isE ? w : (w - KCODE);
    const float4* p = (const float4*)(isE ? (E + (size_t)r * DDIM) : (X + (size_t)r * DDIM));

    float s = 0.f;
#pragma unroll
    for (int i = 0; i < 4; i++) {
        float4 v = p[lane + 32 * i];
        s += v.x * v.x + v.y * v.y + v.z * v.z + v.w * v.w;
    }
#pragma unroll
    for (int o = 16; o > 0; o >>= 1) s += __shfl_xor_sync(0xffffffffu, s, o);
    if (lane == 0) {
        if (isE) g_e2[r] = s;
        else { g_x2[r] = s; g_rowmin[r] = 0xFFFFFFFFu; }
    }

    __nv_bfloat162* dst = (__nv_bfloat162*)((isE ? g_Eb : g_Xb) + (size_t)r * DDIM);
#pragma unroll
    for (int i = 0; i < 4; i++) {
        float4 v = p[lane + 32 * i];
        dst[(lane + 32 * i) * 2 + 0] = __floats2bfloat162_rn(v.x, v.y);
        dst[(lane + 32 * i) * 2 + 1] = __floats2bfloat162_rn(v.z, v.w);
    }
}

// ---------------------------------------------------------------------------
// Kernel 2: bf16 GEMM (128x128 tile, K=512) via ldmatrix + mma.sync.
// Epilogue: u8-quantized score store + per-row exact fp32 atomicMin.
// (Identical mainloop to the best-measured R7 kernel.)
// ---------------------------------------------------------------------------
__global__ __launch_bounds__(256, 2) void vq_mma_kernel() {
    extern __shared__ char smem[];
    const uint32_t sb = smem_u32(smem);
    const int tid = threadIdx.x;
    const int wid = tid >> 5, lane = tid & 31;
    const int g = lane >> 2, tig = lane & 3;
    const int wm = wid & 3, wn = wid >> 2;          // warp grid 4 x 2
    const int rt = blockIdx.x >> 6;                 // col-tile fastest (L2 reuse)
    const int ct = blockIdx.x & 63;
    const int row0 = rt * TM;
    const int col0 = ct * TN;

    auto stage_cp = [&](int s, int ks) {
#pragma unroll
        for (int i = 0; i < 4; i++) {               // A: 1024 16B chunks
            int u = tid + 256 * i, row = u >> 3, c = u & 7;
            const void* src = g_Xb + (size_t)(row0 + row) * DDIM + ks + c * 8;
            uint32_t dst = sb + (uint32_t)s * STAGE_BYTES +
                           (uint32_t)(row * 128 + (c ^ (row & 7)) * 16);
            CP_ASYNC16(dst, src);
        }
#pragma unroll
        for (int i = 0; i < 4; i++) {               // B: 1024 16B chunks
            int u = tid + 256 * i, row = u >> 3, c = u & 7;
            const void* src = g_Eb + (size_t)(col0 + row) * DDIM + ks + c * 8;
            uint32_t dst = sb + B_OFF + (uint32_t)s * STAGE_BYTES +
                           (uint32_t)(row * 128 + (c ^ (row & 7)) * 16);
            CP_ASYNC16(dst, src);
        }
    };

    const int lrow = lane & 7, sel = lane >> 3;
    int arow[2]; const int acb = sel >> 1;
#pragma unroll
    for (int mt = 0; mt < 2; mt++) arow[mt] = wm * 32 + mt * 16 + lrow + (sel & 1) * 8;
    int brow[4]; const int bcb = sel & 1;
#pragma unroll
    for (int ntp = 0; ntp < 4; ntp++) brow[ntp] = wn * 64 + ntp * 16 + (sel >> 1) * 8 + lrow;

    float acc[2][8][4];
#pragma unroll
    for (int mt = 0; mt < 2; mt++)
#pragma unroll
        for (int nt = 0; nt < 8; nt++)
#pragma unroll
            for (int q = 0; q < 4; q++) acc[mt][nt][q] = 0.f;

    stage_cp(0, 0);  CP_COMMIT();
    stage_cp(1, KB); CP_COMMIT();

    for (int ks = 0; ks < NKS; ks++) {
        CP_WAIT1();
        __syncthreads();
        if (ks < NKS - 2) stage_cp((ks + 2) % NSTAGE, (ks + 2) * KB);
        CP_COMMIT();

        const int buf = ks % NSTAGE;
        const uint32_t As = sb + (uint32_t)buf * STAGE_BYTES;
        const uint32_t Bs = sb + B_OFF + (uint32_t)buf * STAGE_BYTES;

#pragma unroll
        for (int s16 = 0; s16 < 4; s16++) {
            uint32_t a[2][4];
#pragma unroll
            for (int mt = 0; mt < 2; mt++) {
                int c = 2 * s16 + acb;
                uint32_t ad = As + arow[mt] * 128 + ((c ^ (arow[mt] & 7)) * 16);
                LDSM_X4(a[mt][0], a[mt][1], a[mt][2], a[mt][3], ad);
            }
            uint32_t b[8][2];
#pragma unroll
            for (int ntp = 0; ntp < 4; ntp++) {
                int c = 2 * s16 + bcb;
                uint32_t bd = Bs + brow[ntp] * 128 + ((c ^ (brow[ntp] & 7)) * 16);
                LDSM_X4(b[2 * ntp][0], b[2 * ntp][1], b[2 * ntp + 1][0], b[2 * ntp + 1][1], bd);
            }
#pragma unroll
            for (int nt = 0; nt < 8; nt++) {
                mma16(acc[0][nt], a[0], b[nt]);
                mma16(acc[1][nt], a[1], b[nt]);
            }
        }
    }

    // ---- epilogue: score = e2 - 2*dot -> u8 store + exact fp32 row min ----
#pragma unroll
    for (int mt = 0; mt < 2; mt++) {
#pragma unroll
        for (int rr = 0; rr < 2; rr++) {
            int row = row0 + wm * 32 + mt * 16 + g + rr * 8;
            uint8_t* srow = g_score8 + ((size_t)row << 13);
            float rmin = CUDART_INF_F;
#pragma unroll
            for (int nt = 0; nt < 8; nt++) {
                int col = col0 + wn * 64 + nt * 8 + 2 * tig;
                float s0 = __ldg(&g_e2[col])     - 2.0f * acc[mt][nt][rr * 2];
                float s1 = __ldg(&g_e2[col + 1]) - 2.0f * acc[mt][nt][rr * 2 + 1];
                rmin = fminf(rmin, fminf(s0, s1));
                int q0 = min(255, max(0, __float2int_rn((s0 - Q_OFF) * Q_INV)));
                int q1 = min(255, max(0, __float2int_rn((s1 - Q_OFF) * Q_INV)));
                *(uint16_t*)(srow + col) = (uint16_t)(q0 | (q1 << 8));
            }
            rmin = fminf(rmin, __shfl_xor_sync(0xffffffffu, rmin, 1));
            rmin = fminf(rmin, __shfl_xor_sync(0xffffffffu, rmin, 2));
            if (tig == 0) atomicMin(&g_rowmin[row], fkey(rmin));
        }
    }
}

// ---------------------------------------------------------------------------
// Kernel 3: single-pass u8 rescue + fused gather/STE. One warp per row.
// Byte threshold is conservative (+1); exact dist form byte-identical to the
// rel_err==0.0-proven path decides among candidates.
// ---------------------------------------------------------------------------
__global__ __launch_bounds__(256) void rescue_gather_kernel(
    const float* __restrict__ X, const float* __restrict__ E,
    float* __restrict__ out) {
    int w    = (blockIdx.x * blockDim.x + threadIdx.x) >> 5;
    int lane = threadIdx.x & 31;
    if (w >= NROWS) return;
    const int row = w;
    const uint4* sv = (const uint4*)(g_score8 + ((size_t)row << 13));

    const float Tf = funkey(g_rowmin[row]) + MARGIN;
    int Tb = min(255, max(0, (int)((Tf - Q_OFF) * Q_INV) + 1));
    const unsigned Tb4 = (unsigned)Tb * 0x01010101u;

    const float x2v = g_x2[row];
    const float* xr = X + (size_t)row * DDIM;
    unsigned long long best = ~0ull;

    for (int it = 0; it < 16; it++) {               // 16 scores per uint4
        uint4 v = __ldg(&sv[lane + 32 * it]);
        unsigned m4 = __vminu4(__vminu4(v.x, v.y), __vminu4(v.z, v.w));
        if (__vcmpleu4(m4, Tb4)) {                  // any byte <= Tb (rare)
            unsigned wv[4] = {v.x, v.y, v.z, v.w};
#pragma unroll
            for (int q = 0; q < 4; q++) {
#pragma unroll
                for (int j = 0; j < 4; j++) {
                    int b = (wv[q] >> (8 * j)) & 0xff;
                    if (b <= Tb) {
                        int k = (lane + 32 * it) * 16 + q * 4 + j;
                        const float* er = E + (size_t)k * DDIM;
                        float acc = 0.f;
                        for (int d = 0; d < DDIM; d++) acc += xr[d] * er[d];
                        float t    = x2v + g_e2[k];
                        float dist = t - 2.0f * acc;   // exact R1-form dist
                        unsigned long long p =
                            ((unsigned long long)__float_as_uint(dist) << 32) | (unsigned)k;
                        best = (p < best) ? p : best;
                    }
                }
            }
        }
    }
#pragma unroll
    for (int o = 16; o > 0; o >>= 1) {
        unsigned long long q = __shfl_xor_sync(0xffffffffu, best, o);
        best = (q < best) ? q : best;
    }
    const int c = (int)(unsigned)(best & 0xffffffffull);

    // fused gather + STE rounding: out = x + (e - x)
    const float4* ep = (const float4*)(E + (size_t)c * DDIM);
    const float4* xp = (const float4*)xr;
    float4* op = (float4*)(out + (size_t)row * DDIM);
#pragma unroll
    for (int i = 0; i < 4; i++) {
        float4 e = ep[lane + 32 * i];
        float4 x = xp[lane + 32 * i];
        float4 o;
        o.x = __fadd_rn(x.x, __fsub_rn(e.x, x.x));
        o.y = __fadd_rn(x.y, __fsub_rn(e.y, x.y));
        o.z = __fadd_rn(x.z, __fsub_rn(e.z, x.z));
        o.w = __fadd_rn(x.w, __fsub_rn(e.w, x.w));
        op[lane + 32 * i] = o;
    }
}

// ---------------------------------------------------------------------------
extern "C" void kernel_launch(void* const* d_in, const int* in_sizes, int n_in,
                              void* d_out, int out_size) {
    const float* X = (const float*)d_in[0];
    const float* E = (const float*)d_in[1];
    float* out = (float*)d_out;

    cudaFuncSetAttribute(vq_mma_kernel, cudaFuncAttributeMaxDynamicSharedMemorySize,
                         SMEM_BYTES);

    int warps = KCODE + NROWS;
    prep_kernel<<<(warps * 32 + 255) / 256, 256>>>(X, E);
    vq_mma_kernel<<<NRT * NCT, 256, SMEM_BYTES>>>();
    rescue_gather_kernel<<<NROWS / 8, 256>>>(X, E, out);
}